// round 15
// baseline (speedup 1.0000x reference)
#include <cuda_runtime.h>
#include <math.h>

#define IMG_H 1088
#define IMG_W 1920
#define BATCH 8
#define TW 96      // tile width
#define TH 32      // tile height
#define NT 768

#define WI 112  // s_img stride; 112 cols loaded: [bx-8, bx+104)
#define WT 104  // s_tmp stride (102 used)
#define WB 104  // s_blur stride (102 used)
#define WM 102  // s_mag/gx/gy stride (100 used)
#define WN 100  // s_thin stride (98 used)

// Lifetime-packed dynamic smem layout (floats):
//   img [0,4928)  tmp [4928,9504)            (dead after stage 1b)
//   gx  [0,3672)  gy [3672,7344)  mag [7344,11016)   (overlay img/tmp)
//   thin[11016,14416)  blur [14416,18368)
// Max live = 18368 floats = 73472 B -> 2 CTAs/SM @ 768 thr = 48 warps.
#define OFF_IMG  0
#define OFF_TMP  4928
#define OFF_GX   0
#define OFF_GY   3672
#define OFF_MAG  7344
#define OFF_THIN 11016
#define OFF_BLUR 14416
#define SM_FLOATS 18368
#define SM_BYTES (SM_FLOATS * 4)

// cephes-style atan2, max err ~1e-7 rad
__device__ __forceinline__ float fast_atan2(float y, float x) {
    float ax = fabsf(x), ay = fabsf(y);
    float mx = fmaxf(ax, ay), mn = fminf(ax, ay);
    float t = __fdividef(mn, mx);
    if (mx == 0.0f) t = 0.0f;
    bool red = t > 0.4142135624f;
    float tr = __fdividef(t - 1.0f, t + 1.0f);
    float u = red ? tr : t;
    float z = u * u;
    float p = ((8.05374449538e-2f * z - 1.38776856032e-1f) * z
               + 1.99777106478e-1f) * z - 3.33329491539e-1f;
    float a = fmaf(p * z, u, u);
    if (red) a += 0.7853981634f;
    if (ay > ax) a = 1.5707963268f - a;
    if (x < 0.0f) a = 3.1415926536f - a;
    return (y < 0.0f) ? -a : a;
}

__global__ __launch_bounds__(NT, 2) void canny_kernel(
    const float* __restrict__ img,
    const float* __restrict__ gk,
    float* __restrict__ out,
    long long N)
{
    extern __shared__ __align__(16) float sbuf[];
    __shared__ float s_r[7], s_c[7];
    float* s_img  = sbuf + OFF_IMG;
    float* s_blur = sbuf + OFF_BLUR;
    float* s_mag  = sbuf + OFF_MAG;
    float* s_thin = sbuf + OFF_THIN;
    float* s_gx   = sbuf + OFF_GX;   // overlays dead img
    float* s_gy   = sbuf + OFF_GY;   // overlays dead img/tmp

    const int tid = threadIdx.x;
    const int bx = blockIdx.x * TW;
    const int by = blockIdx.y * TH;
    const int b  = blockIdx.z;
    const float* ip = img + (long long)b * (IMG_H * IMG_W);

    if (tid < 7) {
        // gaussian is a normalized outer product: k[i][j] = k[i][4]*k[4][j]/k[4][4]
        float s = sqrtf(gk[4 * 7 + 4]);
        s_r[tid] = gk[tid * 7 + 4] / s;   // vertical factor
        s_c[tid] = gk[4 * 7 + tid] / s;   // horizontal factor
    }

    // ---- stage 0: load img cols [bx-8, bx+104) (112 cols) x rows [by-6, by+38) ----
    if (bx >= 8 && bx + 104 <= IMG_W) {
        float4* img4 = (float4*)s_img;
        for (int idx = tid; idx < 44 * 28; idx += NT) {
            int r = idx / 28, v = idx - r * 28;
            int gy = by - 6 + r;
            float4 val = make_float4(0.f, 0.f, 0.f, 0.f);
            if ((unsigned)gy < IMG_H)
                val = *(const float4*)(ip + (long long)gy * IMG_W + (bx - 8) + 4 * v);
            img4[r * (WI / 4) + v] = val;
        }
    } else {
        for (int idx = tid; idx < 44 * 112; idx += NT) {
            int r = idx / 112, c = idx - r * 112;
            int gy = by - 6 + r, gx = bx - 8 + c;
            float v = 0.0f;
            if ((unsigned)gy < IMG_H && (unsigned)gx < IMG_W)
                v = ip[(long long)gy * IMG_W + gx];
            s_img[r * WI + c] = v;
        }
    }
    __syncthreads();

    const float c0 = s_c[0], c1 = s_c[1], c2 = s_c[2], c3 = s_c[3],
                c4 = s_c[4], c5 = s_c[5], c6 = s_c[6];
    const float r0 = s_r[0], r1 = s_r[1], r2 = s_r[2], r3 = s_r[3],
                r4 = s_r[4], r5 = s_r[5], r6 = s_r[6];

    // ---- stage 1a: horizontal 7-tap, 44 rows x 51 col-pairs (102 cols) ----
    {
        const float2* img2 = (const float2*)s_img;
        float2* tmp2 = (float2*)(sbuf + OFF_TMP);
        for (int idx = tid; idx < 44 * 51; idx += NT) {
            int r = idx / 51, p = idx - r * 51;
            // tmp cols 2p,2p+1 (global bx-3+2p) need img locals 2p+2..2p+9
            const float2* row = img2 + r * (WI / 2) + (p + 1);
            float2 A = row[0], B = row[1], C = row[2], D = row[3];
            float o0 = c0*A.x + c1*A.y + c2*B.x + c3*B.y + c4*C.x + c5*C.y + c6*D.x;
            float o1 = c0*A.y + c1*B.x + c2*B.y + c3*C.x + c4*C.y + c5*D.x + c6*D.y;
            tmp2[r * (WT / 2) + p] = make_float2(o0, o1);
        }
    }
    __syncthreads();

    // ---- stage 1b: vertical 7-tap -> blur 38x102; 51 pairs x 10 row-blocks ----
    {
        const float2* tmp2 = (const float2*)(sbuf + OFF_TMP);
        float2* blur2 = (float2*)s_blur;
        for (int idx = tid; idx < 51 * 10; idx += NT) {
            int p = idx % 51, rb = idx / 51;
            int rr = rb * 4;
            float2 tv[10];
            #pragma unroll
            for (int i = 0; i < 10; i++)
                tv[i] = (rr + i < 44) ? tmp2[(rr + i) * (WT / 2) + p]
                                      : make_float2(0.f, 0.f);
            int gx0 = bx - 3 + 2 * p;
            bool cok0 = (unsigned)gx0 < IMG_W;
            bool cok1 = (unsigned)(gx0 + 1) < IMG_W;
            #pragma unroll
            for (int i = 0; i < 4; i++) {
                int r = rr + i;
                if (r < 38) {
                    float vx = r0*tv[i].x + r1*tv[i+1].x + r2*tv[i+2].x + r3*tv[i+3].x
                             + r4*tv[i+4].x + r5*tv[i+5].x + r6*tv[i+6].x;
                    float vy = r0*tv[i].y + r1*tv[i+1].y + r2*tv[i+2].y + r3*tv[i+3].y
                             + r4*tv[i+4].y + r5*tv[i+5].y + r6*tv[i+6].y;
                    int gy = by - 3 + r;
                    bool rok = (unsigned)gy < IMG_H;
                    float2 o;
                    o.x = (rok && cok0) ? vx : 0.0f;
                    o.y = (rok && cok1) ? vy : 0.0f;
                    blur2[r * (WB / 2) + p] = o;
                }
            }
        }
    }
    __syncthreads();

    // ---- stage 2: sobel -> mag (masked) + gx,gy cached; 50 pairs x 9 blocks ----
    {
        const float2* blur2 = (const float2*)s_blur;
        float2* mag2 = (float2*)s_mag;
        float2* gx2  = (float2*)s_gx;
        float2* gy2  = (float2*)s_gy;
        for (int idx = tid; idx < 50 * 9; idx += NT) {
            int p = idx % 50, rb = idx / 50;
            int rr = rb * 4;
            float P0[6], P1[6], Q0[6], Q1[6];
            #pragma unroll
            for (int i = 0; i < 6; i++) {
                float2 e = blur2[(rr + i) * (WB / 2) + p];
                float2 f = blur2[(rr + i) * (WB / 2) + p + 1];
                float a = e.x, bb = e.y, cc = f.x, d = f.y;
                P0[i] = a - cc;           P1[i] = bb - d;
                Q0[i] = a + 2.0f*bb + cc; Q1[i] = bb + 2.0f*cc + d;
            }
            int gxp0 = bx - 2 + 2 * p;
            bool cok0 = (unsigned)gxp0 < IMG_W;
            bool cok1 = (unsigned)(gxp0 + 1) < IMG_W;
            #pragma unroll
            for (int i = 0; i < 4; i++) {
                int r = rr + i;
                float gxa = P0[i] + 2.0f*P0[i+1] + P0[i+2];
                float gya = Q0[i] - Q0[i+2];
                float gxb = P1[i] + 2.0f*P1[i+1] + P1[i+2];
                float gyb = Q1[i] - Q1[i+2];
                float ma = sqrtf(gxa*gxa + gya*gya);
                float mb = sqrtf(gxb*gxb + gyb*gyb);
                int gy = by - 2 + r;
                bool rok = (unsigned)gy < IMG_H;
                float2 om;
                om.x = (rok && cok0) ? ma : 0.0f;
                om.y = (rok && cok1) ? mb : 0.0f;
                mag2[r * (WM / 2) + p] = om;
                gx2 [r * (WM / 2) + p] = make_float2(gxa, gxb);
                gy2 [r * (WM / 2) + p] = make_float2(gya, gyb);
            }
        }
    }
    __syncthreads();

    // ---- stage 3: non-max suppression -> thin; 49 pairs x 9 row-blocks ----
    {
        const float2* mag2 = (const float2*)s_mag;
        float2* thin2 = (float2*)s_thin;
        for (int idx = tid; idx < 49 * 9; idx += NT) {
            int p = idx % 49, rb = idx / 49;
            int rr = rb * 4;
            float P0[6], P1[6], Q0[6], Q1[6], MB[6], MC[6];
            #pragma unroll
            for (int i = 0; i < 6; i++) {
                float2 e = make_float2(0.f, 0.f), f = make_float2(0.f, 0.f);
                if (rr + i < 36) {
                    e = mag2[(rr + i) * (WM / 2) + p];
                    f = mag2[(rr + i) * (WM / 2) + p + 1];
                }
                float a = e.x, bb = e.y, cc = f.x, d = f.y;
                P0[i] = a - cc;           P1[i] = bb - d;
                Q0[i] = a + 2.0f*bb + cc; Q1[i] = bb + 2.0f*cc + d;
                MB[i] = bb; MC[i] = cc;
            }
            int gxp0 = bx - 1 + 2 * p;
            bool cok0 = (unsigned)gxp0 < IMG_W;
            bool cok1 = (unsigned)(gxp0 + 1) < IMG_W;
            #pragma unroll
            for (int i = 0; i < 4; i++) {
                int r = rr + i;
                if (r < 34) {
                    float sxa = P0[i] + 2.0f*P0[i+1] + P0[i+2];
                    float sya = Q0[i] - Q0[i+2];
                    float ma  = MB[i+1];
                    float va = (ma >= sxa && ma >= sya) ? ma : 0.0f;
                    float sxb = P1[i] + 2.0f*P1[i+1] + P1[i+2];
                    float syb = Q1[i] - Q1[i+2];
                    float mbv = MC[i+1];
                    float vb = (mbv >= sxb && mbv >= syb) ? mbv : 0.0f;
                    int gy = by - 1 + r;
                    bool rok = (unsigned)gy < IMG_H;
                    float2 o;
                    o.x = (rok && cok0) ? va : 0.0f;
                    o.y = (rok && cok1) ? vb : 0.0f;
                    thin2[r * (WN / 2) + p] = o;
                }
            }
        }
    }
    __syncthreads();

    // ---- stage 4: hysteresis + 5 plane writes; exactly 1 task per thread ----
    {
        int c  = tid % 96;        // output column (0..95)
        int rb = tid / 96;        // row block (0..7)
        int rr = rb * 4;

        int sb[6][3];
        #pragma unroll
        for (int i = 0; i < 6; i++) {
            const float* row = s_thin + (rr + i) * WN + c;
            sb[i][0] = row[0] > 3.0f;
            sb[i][1] = row[1] > 3.0f;
            sb[i][2] = row[2] > 3.0f;
        }

        long long obase = (long long)b * (IMG_H * IMG_W)
                        + (long long)(by + rr) * IMG_W + (bx + c);
        #pragma unroll
        for (int i = 0; i < 4; i++) {
            float blv = s_blur[(rr + i + 3) * WB + (c + 3)];
            float mv  = s_mag [(rr + i + 2) * WM + (c + 2)];
            float gxv = s_gx  [(rr + i + 2) * WM + (c + 2)];
            float gyv = s_gy  [(rr + i + 2) * WM + (c + 2)];
            float tc  = s_thin[(rr + i + 1) * WN + (c + 1)];

            bool strong = tc > 3.0f;
            bool weak   = (tc > 1.0f) && (tc <= 3.0f);
            int full9 = sb[i][0] + sb[i][1] + sb[i][2]
                      + sb[i+1][0] + sb[i+1][1] + sb[i+1][2]
                      + sb[i+2][0] + sb[i+2][1] + sb[i+2][2];
            // conv with hyst_k (center -8) > 0  <=>  full9 - 9*center_strong > 0
            bool sn   = (full9 - 9 * sb[i+1][1]) > 0;
            bool edge = strong || (weak && sn);

            long long o = obase + (long long)i * IMG_W;
            out[o]         = blv;
            out[N + o]     = mv;
            out[2 * N + o] = fast_atan2(gyv, gxv);
            out[3 * N + o] = tc;
            out[4 * N + o] = edge ? 1.0f : 0.0f;
        }
    }
}

extern "C" void kernel_launch(void* const* d_in, const int* in_sizes, int n_in,
                              void* d_out, int out_size) {
    const float* img = (const float*)d_in[0];
    const float* gk  = (const float*)d_in[1];
    float* out = (float*)d_out;
    long long N = (long long)out_size / 5;   // 5 concatenated planes
    // opt-in to >48KB dynamic smem (idempotent host call, not an allocation)
    cudaFuncSetAttribute(canny_kernel,
                         cudaFuncAttributeMaxDynamicSharedMemorySize, SM_BYTES);
    dim3 grid(IMG_W / TW, IMG_H / TH, BATCH);
    canny_kernel<<<grid, NT, SM_BYTES>>>(img, gk, out, N);
}

// round 16
// speedup vs baseline: 1.0571x; 1.0571x over previous
#include <cuda_runtime.h>
#include <math.h>

#define IMG_H 1088
#define IMG_W 1920
#define BATCH 8
#define TW 64      // tile width
#define TH 32      // tile height
#define NT 512

#define WI 80   // s_img stride; 80 cols loaded: [bx-8, bx+72)
#define WT 72   // s_tmp stride (70 used; 72 written by quad stage)
#define WB 72   // s_blur stride (70 used)
#define WM 70   // s_mag/gx/gy stride (68 used)
#define WN 68   // s_thin stride (66 used)

// Lifetime-packed dynamic smem layout (floats):
//   img [0,3520)  tmp [3520,6688)            (dead after stage 1b)
//   gx  [0,2520)  gy [2520,5040)  mag [5040,7560)   (overlay img/tmp)
//   thin[7560,9872)  blur [9872,12608)
// Max live = 12608 floats = 50432 B -> 3 CTAs/SM @ 512 thr = 48 warps.
#define OFF_IMG  0
#define OFF_TMP  3520
#define OFF_GX   0
#define OFF_GY   2520
#define OFF_MAG  5040
#define OFF_THIN 7560
#define OFF_BLUR 9872
#define SM_FLOATS 12608
#define SM_BYTES (SM_FLOATS * 4)

// cephes-style atan2, max err ~1e-7 rad
__device__ __forceinline__ float fast_atan2(float y, float x) {
    float ax = fabsf(x), ay = fabsf(y);
    float mx = fmaxf(ax, ay), mn = fminf(ax, ay);
    float t = __fdividef(mn, mx);
    if (mx == 0.0f) t = 0.0f;
    bool red = t > 0.4142135624f;
    float tr = __fdividef(t - 1.0f, t + 1.0f);
    float u = red ? tr : t;
    float z = u * u;
    float p = ((8.05374449538e-2f * z - 1.38776856032e-1f) * z
               + 1.99777106478e-1f) * z - 3.33329491539e-1f;
    float a = fmaf(p * z, u, u);
    if (red) a += 0.7853981634f;
    if (ay > ax) a = 1.5707963268f - a;
    if (x < 0.0f) a = 3.1415926536f - a;
    return (y < 0.0f) ? -a : a;
}

__global__ __launch_bounds__(NT, 3) void canny_kernel(
    const float* __restrict__ img,
    const float* __restrict__ gk,
    float* __restrict__ out,
    long long N)
{
    extern __shared__ __align__(16) float sbuf[];
    __shared__ float s_r[7], s_c[7];
    float* s_img  = sbuf + OFF_IMG;
    float* s_blur = sbuf + OFF_BLUR;
    float* s_mag  = sbuf + OFF_MAG;
    float* s_thin = sbuf + OFF_THIN;
    float* s_gx   = sbuf + OFF_GX;   // overlays dead img
    float* s_gy   = sbuf + OFF_GY;   // overlays dead img/tmp

    const int tid = threadIdx.x;
    const int bx = blockIdx.x * TW;
    const int by = blockIdx.y * TH;
    const int b  = blockIdx.z;
    const float* ip = img + (long long)b * (IMG_H * IMG_W);

    if (tid < 7) {
        // gaussian is a normalized outer product: k[i][j] = k[i][4]*k[4][j]/k[4][4]
        float s = sqrtf(gk[4 * 7 + 4]);
        s_r[tid] = gk[tid * 7 + 4] / s;   // vertical factor
        s_c[tid] = gk[4 * 7 + tid] / s;   // horizontal factor
    }

    // ---- stage 0: load img cols [bx-8, bx+72) (80 cols) x rows [by-6, by+38) ----
    if (bx >= 8 && bx + 72 <= IMG_W) {
        float4* img4 = (float4*)s_img;
        for (int idx = tid; idx < 44 * 20; idx += NT) {
            int r = idx / 20, v = idx - r * 20;
            int gy = by - 6 + r;
            float4 val = make_float4(0.f, 0.f, 0.f, 0.f);
            if ((unsigned)gy < IMG_H)
                val = *(const float4*)(ip + (long long)gy * IMG_W + (bx - 8) + 4 * v);
            img4[r * (WI / 4) + v] = val;
        }
    } else {
        for (int idx = tid; idx < 44 * 80; idx += NT) {
            int r = idx / 80, c = idx - r * 80;
            int gy = by - 6 + r, gx = bx - 8 + c;
            float v = 0.0f;
            if ((unsigned)gy < IMG_H && (unsigned)gx < IMG_W)
                v = ip[(long long)gy * IMG_W + gx];
            s_img[r * WI + c] = v;
        }
    }
    __syncthreads();

    const float c0 = s_c[0], c1 = s_c[1], c2 = s_c[2], c3 = s_c[3],
                c4 = s_c[4], c5 = s_c[5], c6 = s_c[6];
    const float r0 = s_r[0], r1 = s_r[1], r2 = s_r[2], r3 = s_r[3],
                r4 = s_r[4], r5 = s_r[5], r6 = s_r[6];

    // ---- stage 1a: horizontal 7-tap, float4-quad: 44 rows x 18 quads ----
    // tmp cols 4q..4q+3 need img locals 4q+2..4q+11 c [4q, 4q+12) = 3 float4s
    {
        const float4* img4 = (const float4*)s_img;
        float4* tmp4 = (float4*)(sbuf + OFF_TMP);
        for (int idx = tid; idx < 44 * 18; idx += NT) {
            int r = idx / 18, q = idx - r * 18;
            const float4* row = img4 + r * (WI / 4) + q;
            float4 A = row[0], B = row[1], C = row[2];
            float o0 = c0*A.z + c1*A.w + c2*B.x + c3*B.y + c4*B.z + c5*B.w + c6*C.x;
            float o1 = c0*A.w + c1*B.x + c2*B.y + c3*B.z + c4*B.w + c5*C.x + c6*C.y;
            float o2 = c0*B.x + c1*B.y + c2*B.z + c3*B.w + c4*C.x + c5*C.y + c6*C.z;
            float o3 = c0*B.y + c1*B.z + c2*B.w + c3*C.x + c4*C.y + c5*C.z + c6*C.w;
            tmp4[r * (WT / 4) + q] = make_float4(o0, o1, o2, o3);
        }
    }
    __syncthreads();

    // ---- stage 1b: vertical 7-tap -> blur 38x70; 35 pairs x 10 row-blocks ----
    {
        const float2* tmp2 = (const float2*)(sbuf + OFF_TMP);
        float2* blur2 = (float2*)s_blur;
        for (int idx = tid; idx < 35 * 10; idx += NT) {
            int p = idx % 35, rb = idx / 35;
            int rr = rb * 4;
            float2 tv[10];
            #pragma unroll
            for (int i = 0; i < 10; i++)
                tv[i] = (rr + i < 44) ? tmp2[(rr + i) * (WT / 2) + p]
                                      : make_float2(0.f, 0.f);
            int gx0 = bx - 3 + 2 * p;
            bool cok0 = (unsigned)gx0 < IMG_W;
            bool cok1 = (unsigned)(gx0 + 1) < IMG_W;
            #pragma unroll
            for (int i = 0; i < 4; i++) {
                int r = rr + i;
                if (r < 38) {
                    float vx = r0*tv[i].x + r1*tv[i+1].x + r2*tv[i+2].x + r3*tv[i+3].x
                             + r4*tv[i+4].x + r5*tv[i+5].x + r6*tv[i+6].x;
                    float vy = r0*tv[i].y + r1*tv[i+1].y + r2*tv[i+2].y + r3*tv[i+3].y
                             + r4*tv[i+4].y + r5*tv[i+5].y + r6*tv[i+6].y;
                    int gy = by - 3 + r;
                    bool rok = (unsigned)gy < IMG_H;
                    float2 o;
                    o.x = (rok && cok0) ? vx : 0.0f;
                    o.y = (rok && cok1) ? vy : 0.0f;
                    blur2[r * (WB / 2) + p] = o;
                }
            }
        }
    }
    __syncthreads();

    // ---- stage 2: sobel -> mag (masked) + gx,gy cached; 34 pairs x 9 blocks ----
    {
        const float2* blur2 = (const float2*)s_blur;
        float2* mag2 = (float2*)s_mag;
        float2* gx2  = (float2*)s_gx;
        float2* gy2  = (float2*)s_gy;
        for (int idx = tid; idx < 34 * 9; idx += NT) {
            int p = idx % 34, rb = idx / 34;
            int rr = rb * 4;
            float P0[6], P1[6], Q0[6], Q1[6];
            #pragma unroll
            for (int i = 0; i < 6; i++) {
                float2 e = blur2[(rr + i) * (WB / 2) + p];
                float2 f = blur2[(rr + i) * (WB / 2) + p + 1];
                float a = e.x, bb = e.y, cc = f.x, d = f.y;
                P0[i] = a - cc;           P1[i] = bb - d;
                Q0[i] = a + 2.0f*bb + cc; Q1[i] = bb + 2.0f*cc + d;
            }
            int gxp0 = bx - 2 + 2 * p;
            bool cok0 = (unsigned)gxp0 < IMG_W;
            bool cok1 = (unsigned)(gxp0 + 1) < IMG_W;
            #pragma unroll
            for (int i = 0; i < 4; i++) {
                int r = rr + i;
                float gxa = P0[i] + 2.0f*P0[i+1] + P0[i+2];
                float gya = Q0[i] - Q0[i+2];
                float gxb = P1[i] + 2.0f*P1[i+1] + P1[i+2];
                float gyb = Q1[i] - Q1[i+2];
                float ma = sqrtf(gxa*gxa + gya*gya);
                float mb = sqrtf(gxb*gxb + gyb*gyb);
                int gy = by - 2 + r;
                bool rok = (unsigned)gy < IMG_H;
                float2 om;
                om.x = (rok && cok0) ? ma : 0.0f;
                om.y = (rok && cok1) ? mb : 0.0f;
                mag2[r * (WM / 2) + p] = om;
                gx2 [r * (WM / 2) + p] = make_float2(gxa, gxb);
                gy2 [r * (WM / 2) + p] = make_float2(gya, gyb);
            }
        }
    }
    __syncthreads();

    // ---- stage 3: non-max suppression -> thin; 33 pairs x 9 row-blocks ----
    {
        const float2* mag2 = (const float2*)s_mag;
        float2* thin2 = (float2*)s_thin;
        for (int idx = tid; idx < 33 * 9; idx += NT) {
            int p = idx % 33, rb = idx / 33;
            int rr = rb * 4;
            float P0[6], P1[6], Q0[6], Q1[6], MB[6], MC[6];
            #pragma unroll
            for (int i = 0; i < 6; i++) {
                float2 e = make_float2(0.f, 0.f), f = make_float2(0.f, 0.f);
                if (rr + i < 36) {
                    e = mag2[(rr + i) * (WM / 2) + p];
                    f = mag2[(rr + i) * (WM / 2) + p + 1];
                }
                float a = e.x, bb = e.y, cc = f.x, d = f.y;
                P0[i] = a - cc;           P1[i] = bb - d;
                Q0[i] = a + 2.0f*bb + cc; Q1[i] = bb + 2.0f*cc + d;
                MB[i] = bb; MC[i] = cc;
            }
            int gxp0 = bx - 1 + 2 * p;
            bool cok0 = (unsigned)gxp0 < IMG_W;
            bool cok1 = (unsigned)(gxp0 + 1) < IMG_W;
            #pragma unroll
            for (int i = 0; i < 4; i++) {
                int r = rr + i;
                if (r < 34) {
                    float sxa = P0[i] + 2.0f*P0[i+1] + P0[i+2];
                    float sya = Q0[i] - Q0[i+2];
                    float ma  = MB[i+1];
                    float va = (ma >= sxa && ma >= sya) ? ma : 0.0f;
                    float sxb = P1[i] + 2.0f*P1[i+1] + P1[i+2];
                    float syb = Q1[i] - Q1[i+2];
                    float mbv = MC[i+1];
                    float vb = (mbv >= sxb && mbv >= syb) ? mbv : 0.0f;
                    int gy = by - 1 + r;
                    bool rok = (unsigned)gy < IMG_H;
                    float2 o;
                    o.x = (rok && cok0) ? va : 0.0f;
                    o.y = (rok && cok1) ? vb : 0.0f;
                    thin2[r * (WN / 2) + p] = o;
                }
            }
        }
    }
    __syncthreads();

    // ---- stage 4: hysteresis + 5 plane writes; 1 column x 4 rows per thread ----
    {
        int c  = tid & 63;        // output column (0..63)
        int rb = tid >> 6;        // row block (0..7)
        int rr = rb * 4;

        int sb[6][3];
        #pragma unroll
        for (int i = 0; i < 6; i++) {
            const float* row = s_thin + (rr + i) * WN + c;
            sb[i][0] = row[0] > 3.0f;
            sb[i][1] = row[1] > 3.0f;
            sb[i][2] = row[2] > 3.0f;
        }

        long long obase = (long long)b * (IMG_H * IMG_W)
                        + (long long)(by + rr) * IMG_W + (bx + c);
        #pragma unroll
        for (int i = 0; i < 4; i++) {
            float blv = s_blur[(rr + i + 3) * WB + (c + 3)];
            float mv  = s_mag [(rr + i + 2) * WM + (c + 2)];
            float gxv = s_gx  [(rr + i + 2) * WM + (c + 2)];
            float gyv = s_gy  [(rr + i + 2) * WM + (c + 2)];
            float tc  = s_thin[(rr + i + 1) * WN + (c + 1)];

            bool strong = tc > 3.0f;
            bool weak   = (tc > 1.0f) && (tc <= 3.0f);
            int full9 = sb[i][0] + sb[i][1] + sb[i][2]
                      + sb[i+1][0] + sb[i+1][1] + sb[i+1][2]
                      + sb[i+2][0] + sb[i+2][1] + sb[i+2][2];
            // conv with hyst_k (center -8) > 0  <=>  full9 - 9*center_strong > 0
            bool sn   = (full9 - 9 * sb[i+1][1]) > 0;
            bool edge = strong || (weak && sn);

            long long o = obase + (long long)i * IMG_W;
            out[o]         = blv;
            out[N + o]     = mv;
            out[2 * N + o] = fast_atan2(gyv, gxv);
            out[3 * N + o] = tc;
            out[4 * N + o] = edge ? 1.0f : 0.0f;
        }
    }
}

extern "C" void kernel_launch(void* const* d_in, const int* in_sizes, int n_in,
                              void* d_out, int out_size) {
    const float* img = (const float*)d_in[0];
    const float* gk  = (const float*)d_in[1];
    float* out = (float*)d_out;
    long long N = (long long)out_size / 5;   // 5 concatenated planes
    // opt-in to >48KB dynamic smem (idempotent host call, not an allocation)
    cudaFuncSetAttribute(canny_kernel,
                         cudaFuncAttributeMaxDynamicSharedMemorySize, SM_BYTES);
    dim3 grid(IMG_W / TW, IMG_H / TH, BATCH);
    canny_kernel<<<grid, NT, SM_BYTES>>>(img, gk, out, N);
}